// round 12
// baseline (speedup 1.0000x reference)
#include <cuda_runtime.h>
#include <cuda_bf16.h>
#include <math.h>
#include <stdint.h>

#define NTOK   16384
#define NH     8
#define HE     512
#define QKVDIM 1536
#define NEWTON 4
#define NITER  16

typedef unsigned long long ull;

// Scratch (static device memory — allocation-free)
__device__ float         g_qkv[NTOK * QKVDIM];  // q (pre-scaled) | k | v
__device__ __nv_bfloat16 g_res_hi[NTOK * HE];
__device__ __nv_bfloat16 g_res_lo[NTOK * HE];
// Pre-split bf16 hi/lo operands (filled once by k_prep)
__device__ __nv_bfloat16 g_xh[NTOK * 64],  g_xl[NTOK * 64];
__device__ __nv_bfloat16 g_wh[1536 * 64],  g_wl[1536 * 64];   // [Wq;Wk;Wv]
__device__ __nv_bfloat16 g_wuh[64 * 512],  g_wul[64 * 512];

// ======================= helpers ===========================================
__device__ __forceinline__ uint32_t smem_u32(const void* p) {
    uint32_t a;
    asm("{ .reg .u64 t; cvta.to.shared.u64 t, %1; cvt.u32.u64 %0, t; }" : "=r"(a) : "l"(p));
    return a;
}
__device__ __forceinline__ void ldsm4(uint32_t& r0, uint32_t& r1, uint32_t& r2, uint32_t& r3,
                                      uint32_t a) {
    asm volatile("ldmatrix.sync.aligned.m8n8.x4.shared.b16 {%0,%1,%2,%3}, [%4];"
                 : "=r"(r0), "=r"(r1), "=r"(r2), "=r"(r3) : "r"(a));
}
__device__ __forceinline__ void mma16816(float* d, uint32_t a0, uint32_t a1, uint32_t a2,
                                         uint32_t a3, uint32_t b0, uint32_t b1) {
    asm volatile(
        "mma.sync.aligned.m16n8k16.row.col.f32.bf16.bf16.f32 "
        "{%0,%1,%2,%3}, {%4,%5,%6,%7}, {%8,%9}, {%0,%1,%2,%3};"
        : "+f"(d[0]), "+f"(d[1]), "+f"(d[2]), "+f"(d[3])
        : "r"(a0), "r"(a1), "r"(a2), "r"(a3), "r"(b0), "r"(b1));
}
__device__ __forceinline__ void split2(float a, float b, uint32_t& hp, uint32_t& lp) {
    __nv_bfloat162 h = __floats2bfloat162_rn(a, b);
    float2 hf = __bfloat1622float2(h);
    __nv_bfloat162 l = __floats2bfloat162_rn(a - hf.x, b - hf.y);
    hp = *reinterpret_cast<uint32_t*>(&h);
    lp = *reinterpret_cast<uint32_t*>(&l);
}

// ---------------- f32x2 packed-math helpers (k_attn) -----------------------
__device__ __forceinline__ ull pack2(float lo, float hi) {
    ull r; asm("mov.b64 %0, {%1, %2};" : "=l"(r) : "f"(lo), "f"(hi)); return r;
}
__device__ __forceinline__ ull dup2(float v) { return pack2(v, v); }
__device__ __forceinline__ float lo2(ull v) {
    float f; asm("{ .reg .b32 hi; mov.b64 {%0, hi}, %1; }" : "=f"(f) : "l"(v)); return f;
}
__device__ __forceinline__ float hi2(ull v) {
    float f; asm("{ .reg .b32 lo; mov.b64 {lo, %0}, %1; }" : "=f"(f) : "l"(v)); return f;
}
__device__ __forceinline__ void ffma2(ull& d, ull a, ull b) {
    asm("fma.rn.f32x2 %0, %1, %2, %0;" : "+l"(d) : "l"(a), "l"(b));
}
__device__ __forceinline__ ull add2(ull a, ull b) {
    ull r; asm("add.rn.f32x2 %0, %1, %2;" : "=l"(r) : "l"(a), "l"(b)); return r;
}
__device__ __forceinline__ ull mul2(ull a, ull b) {
    ull r; asm("mul.rn.f32x2 %0, %1, %2;" : "=l"(r) : "l"(a), "l"(b)); return r;
}
__device__ __forceinline__ float hsum2(ull v) { return lo2(v) + hi2(v); }
__device__ __forceinline__ ull relu2_add(ull x2, ull nt2) {
    ull r;
    asm("{\n\t"
        ".reg .f32 lo, hi;\n\t"
        "add.rn.f32x2 %0, %1, %2;\n\t"
        "mov.b64 {lo, hi}, %0;\n\t"
        "max.f32 lo, lo, 0f00000000;\n\t"
        "max.f32 hi, hi, 0f00000000;\n\t"
        "mov.b64 %0, {lo, hi};\n\t"
        "}" : "=l"(r) : "l"(x2), "l"(nt2));
    return r;
}

// ---------------------------------------------------------------------------
// K0: one-time bf16 hi/lo split of x, [Wq;Wk;Wv], Wu.
// ---------------------------------------------------------------------------
#define NXP  (NTOK * 64 / 2)
#define NWP  (1536 * 64 / 2)
#define NUP  (64 * 512 / 2)
__global__ __launch_bounds__(256) void k_prep(
    const float* __restrict__ x,
    const float* __restrict__ Wq, const float* __restrict__ Wk,
    const float* __restrict__ Wv, const float* __restrict__ Wu)
{
    int idx = blockIdx.x * 256 + threadIdx.x;
    const float* src; __nv_bfloat16* dh; __nv_bfloat16* dl; int p;
    if (idx < NXP)                  { src = x;  dh = g_xh;  dl = g_xl;  p = idx; }
    else if (idx < NXP + NWP) {
        p = idx - NXP;
        int f = p * 2;
        if (f < 32768)      { src = Wq; dh = g_wh; dl = g_wl; }
        else if (f < 65536) { src = Wk - 32768; dh = g_wh; dl = g_wl; }
        else                { src = Wv - 65536; dh = g_wh; dl = g_wl; }
    }
    else if (idx < NXP + NWP + NUP) { p = idx - NXP - NWP; src = Wu; dh = g_wuh; dl = g_wul; }
    else return;
    float2 v = *(const float2*)(src + (size_t)p * 2);
    uint32_t hp, lp;
    split2(v.x, v.y, hp, lp);
    ((uint32_t*)dh)[p] = hp;
    ((uint32_t*)dl)[p] = lp;
}

// ---------------------------------------------------------------------------
// K1 (mma.sync bf16 split): QKV projection, pre-split operands.
// ---------------------------------------------------------------------------
__global__ __launch_bounds__(256) void k_qkv(
    const float* __restrict__ bq, const float* __restrict__ bk,
    const float* __restrict__ bv, const float* __restrict__ alpha_p)
{
    __shared__ __align__(16) __nv_bfloat16 sA[2][128 * 64];
    __shared__ __align__(16) __nv_bfloat16 sB[2][64 * 64];
    const int tid  = threadIdx.x;
    const int bm   = blockIdx.x;
    const int tn   = blockIdx.y;
    const int oBase = tn * 64;

    const float* bias;
    if (tn < 8)       bias = bq;
    else if (tn < 16) bias = bk;
    else              bias = bv;
    const int wBase = oBase & 511;

    for (int idx = tid; idx < 1024; idx += 256) {
        int row = idx >> 3, c = idx & 7;
        size_t so = (size_t)(bm * 128 + row) * 64 + c * 8;
        int off = row * 8 + (c ^ (row & 7));
        ((uint4*)sA[0])[off] = *(const uint4*)(g_xh + so);
        ((uint4*)sA[1])[off] = *(const uint4*)(g_xl + so);
    }
    for (int idx = tid; idx < 512; idx += 256) {
        int row = idx >> 3, c = idx & 7;
        size_t so = (size_t)(tn * 64 + row) * 64 + c * 8;
        int off = row * 8 + (c ^ (row & 7));
        ((uint4*)sB[0])[off] = *(const uint4*)(g_wh + so);
        ((uint4*)sB[1])[off] = *(const uint4*)(g_wl + so);
    }
    __syncthreads();

    const int wid   = tid >> 5, lane = tid & 31;
    const int warpM = wid >> 1, warpN = wid & 1;

    float acc[2][4][4];
    #pragma unroll
    for (int m = 0; m < 2; m++)
        #pragma unroll
        for (int n = 0; n < 4; n++)
            #pragma unroll
            for (int k = 0; k < 4; k++) acc[m][n][k] = 0.f;

    const uint32_t aB[2] = { smem_u32(sA[0]), smem_u32(sA[1]) };
    const uint32_t bB[2] = { smem_u32(sB[0]), smem_u32(sB[1]) };
    const int pa[3] = {0, 1, 0}, pb[3] = {0, 0, 1};

    const int arow0 = warpM * 32 + (lane & 15);
    const int brow0 = warpN * 32 + (lane & 15);
    const int chi   = lane >> 4;

    uint32_t offA[4], offB[4];
    #pragma unroll
    for (int kk = 0; kk < 4; kk++) {
        int cc = kk * 2 + chi;
        offA[kk] = (uint32_t)((arow0 * 8 + (cc ^ (arow0 & 7))) << 4);
        offB[kk] = (uint32_t)((brow0 * 8 + (cc ^ (brow0 & 7))) << 4);
    }

    #pragma unroll
    for (int p = 0; p < 3; p++) {
        uint32_t ab = aB[pa[p]], bb = bB[pb[p]];
        #pragma unroll
        for (int kk = 0; kk < 4; kk++) {
            uint32_t a0, a1, a2, a3, a4, a5, a6, a7;
            ldsm4(a0, a1, a2, a3, ab + offA[kk]);
            ldsm4(a4, a5, a6, a7, ab + offA[kk] + 2048);
            uint32_t b0, b1, b2, b3, b4, b5, b6, b7;
            ldsm4(b0, b1, b2, b3, bb + offB[kk]);
            ldsm4(b4, b5, b6, b7, bb + offB[kk] + 2048);
            mma16816(acc[0][0], a0, a1, a2, a3, b0, b2);
            mma16816(acc[0][1], a0, a1, a2, a3, b1, b3);
            mma16816(acc[0][2], a0, a1, a2, a3, b4, b6);
            mma16816(acc[0][3], a0, a1, a2, a3, b5, b7);
            mma16816(acc[1][0], a4, a5, a6, a7, b0, b2);
            mma16816(acc[1][1], a4, a5, a6, a7, b1, b3);
            mma16816(acc[1][2], a4, a5, a6, a7, b4, b6);
            mma16816(acc[1][3], a4, a5, a6, a7, b5, b7);
        }
    }

    const float am1   = __ldg(alpha_p) - 1.f;
    const float scale = (tn < 8) ? am1 * 0.125f : 1.f;
    const int rbase = bm * 128 + warpM * 32 + (lane >> 2);
    const int cbase = warpN * 32 + (lane & 3) * 2;
    #pragma unroll
    for (int mt = 0; mt < 2; mt++)
        #pragma unroll
        for (int nt = 0; nt < 4; nt++) {
            int col = cbase + nt * 8;
            float bv0 = __ldg(&bias[wBase + col]);
            float bv1 = __ldg(&bias[wBase + col + 1]);
            int row0 = rbase + mt * 16;
            float2 e0 = make_float2((acc[mt][nt][0] + bv0) * scale,
                                    (acc[mt][nt][1] + bv1) * scale);
            float2 e1 = make_float2((acc[mt][nt][2] + bv0) * scale,
                                    (acc[mt][nt][3] + bv1) * scale);
            *(float2*)(g_qkv + (size_t)row0 * QKVDIM + oBase + col)       = e0;
            *(float2*)(g_qkv + (size_t)(row0 + 8) * QKVDIM + oBase + col) = e1;
        }
}

// ---------------------------------------------------------------------------
// K2: scores via mma.sync (A=[q_hi|q_lo], 2 passes B=[k_hi|k_hi],[k_lo|k_lo]
// => exact (q_hi+q_lo)(k_hi+k_lo)), entmax (4 Newton + quad solve), att@V^T.
// 4 tokens/CTA, 256 threads (2 warps per token for the score mma).
// Token smem block: [A|B1|B2 bf16, pitch 24] overlaid later by S fp32
// (pitch 68 floats), plus V fp32 at +17408.  19456 B per token.
// ---------------------------------------------------------------------------
#define TOKB 19456
#define ATTN_SMEM (4 * TOKB)
__global__ __launch_bounds__(256, 2) void k_attn(const float* __restrict__ alpha_p)
{
    extern __shared__ char sm[];
    const int tid   = threadIdx.x;
    const int tok0  = blockIdx.x * 4;
    const int lt    = tid >> 6;
    const int i     = tid & 63;
    const int token = tok0 + lt;

    // ---- fill: q -> A, k -> B1/B2 (bf16 hi/lo), v -> fp32 ----
    for (int idx = tid; idx < 2048; idx += 256) {        // q
        int t = idx >> 9, r = idx & 511;
        float v = g_qkv[(size_t)(tok0 + t) * QKVDIM + r];
        __nv_bfloat16 hb = __float2bfloat16(v);
        __nv_bfloat16 lb = __float2bfloat16(v - __bfloat162float(hb));
        int h = r >> 6, ii = r & 63;
        __nv_bfloat16* A = (__nv_bfloat16*)(sm + t * TOKB);
        A[ii * 24 + h]     = hb;
        A[ii * 24 + h + 8] = lb;
    }
    for (int idx = tid; idx < 2048; idx += 256) {        // k
        int t = idx >> 9, r = idx & 511;
        float v = g_qkv[(size_t)(tok0 + t) * QKVDIM + 512 + r];
        __nv_bfloat16 hb = __float2bfloat16(v);
        __nv_bfloat16 lb = __float2bfloat16(v - __bfloat162float(hb));
        int h = r >> 6, jj = r & 63;
        __nv_bfloat16* B1 = (__nv_bfloat16*)(sm + t * TOKB + 3072);
        __nv_bfloat16* B2 = (__nv_bfloat16*)(sm + t * TOKB + 6144);
        B1[jj * 24 + h]     = hb;
        B1[jj * 24 + h + 8] = hb;
        B2[jj * 24 + h]     = lb;
        B2[jj * 24 + h + 8] = lb;
    }
    for (int idx = tid; idx < 512; idx += 256) {         // v
        int t = idx >> 7, r = idx & 127;
        *(float4*)(sm + t * TOKB + 17408 + r * 16) =
            *(const float4*)(g_qkv + (size_t)(tok0 + t) * QKVDIM + 1024 + r * 4);
    }
    __syncthreads();

    // ---- score mma: each warp does a 64x32 half of one token's S ----
    const int wid = tid >> 5, lane = tid & 31;
    const int mtok = wid >> 1, half = wid & 1;
    {
        uint32_t aBase  = smem_u32(sm + mtok * TOKB);
        uint32_t b1Base = aBase + 3072;
        uint32_t b2Base = aBase + 6144;
        const int lrow = lane & 15, lch = lane >> 4;

        uint32_t a[4][4];
        #pragma unroll
        for (int mt = 0; mt < 4; mt++) {
            uint32_t addr = aBase + (uint32_t)((mt * 16 + lrow) * 48 + lch * 16);
            ldsm4(a[mt][0], a[mt][1], a[mt][2], a[mt][3], addr);
        }
        uint32_t boff0 = (uint32_t)((half * 32 + lrow) * 48 + lch * 16);
        uint32_t boff1 = (uint32_t)((half * 32 + 16 + lrow) * 48 + lch * 16);

        float acc[4][4][4];
        #pragma unroll
        for (int m = 0; m < 4; m++)
            #pragma unroll
            for (int n = 0; n < 4; n++)
                #pragma unroll
                for (int k = 0; k < 4; k++) acc[m][n][k] = 0.f;

        #pragma unroll
        for (int p = 0; p < 2; p++) {
            uint32_t bb = p ? b2Base : b1Base;
            uint32_t b0, b1, b2, b3, b4, b5, b6, b7;
            ldsm4(b0, b1, b2, b3, bb + boff0);
            ldsm4(b4, b5, b6, b7, bb + boff1);
            #pragma unroll
            for (int mt = 0; mt < 4; mt++) {
                mma16816(acc[mt][0], a[mt][0], a[mt][1], a[mt][2], a[mt][3], b0, b2);
                mma16816(acc[mt][1], a[mt][0], a[mt][1], a[mt][2], a[mt][3], b1, b3);
                mma16816(acc[mt][2], a[mt][0], a[mt][1], a[mt][2], a[mt][3], b4, b6);
                mma16816(acc[mt][3], a[mt][0], a[mt][1], a[mt][2], a[mt][3], b5, b7);
            }
        }
        __syncthreads();    // all mma reads of A/B done before S overwrites them

        float* S = (float*)(sm + mtok * TOKB);
        const int sr = lane >> 2, sc = half * 32 + (lane & 3) * 2;
        #pragma unroll
        for (int mt = 0; mt < 4; mt++)
            #pragma unroll
            for (int nt = 0; nt < 4; nt++) {
                int row = mt * 16 + sr, col = sc + nt * 8;
                *(float2*)&S[row * 68 + col]       = make_float2(acc[mt][nt][0], acc[mt][nt][1]);
                *(float2*)&S[(row + 8) * 68 + col] = make_float2(acc[mt][nt][2], acc[mt][nt][3]);
            }
    }
    __syncthreads();

    // ---- reload own row into registers ----
    ull xa2[32];
    {
        const float4* Srow = (const float4*)((const float*)(sm + lt * TOKB) + i * 68);
        #pragma unroll
        for (int p = 0; p < 16; p++) {
            float4 f = Srow[p];
            xa2[2 * p]     = pack2(f.x, f.y);
            xa2[2 * p + 1] = pack2(f.z, f.w);
        }
    }

    const float am1 = alpha_p[0] - 1.f;
    const float inv = 1.f / am1;
    const bool fast = fabsf(inv - 2.f) < 1e-4f;

    float mx = -3.4e38f;
    #pragma unroll
    for (int p = 0; p < 32; p++)
        mx = fmaxf(mx, fmaxf(lo2(xa2[p]), hi2(xa2[p])));

    float tau = mx - 1.f;

    if (fast) {
        for (int it = 0; it < NEWTON; it++) {
            ull nt = dup2(-tau);
            ull s2a = 0ULL, s2b = 0ULL, s2c = 0ULL, s2d = 0ULL;
            ull s1a = 0ULL, s1b = 0ULL, s1c = 0ULL, s1d = 0ULL;
            #pragma unroll
            for (int j = 0; j < 8; j++) {
                ull t;
                t = relu2_add(xa2[j],      nt); ffma2(s2a, t, t); s1a = add2(s1a, t);
                t = relu2_add(xa2[j +  8], nt); ffma2(s2b, t, t); s1b = add2(s1b, t);
                t = relu2_add(xa2[j + 16], nt); ffma2(s2c, t, t); s1c = add2(s1c, t);
                t = relu2_add(xa2[j + 24], nt); ffma2(s2d, t, t); s1d = add2(s1d, t);
            }
            float f  = hsum2(add2(add2(s2a, s2b), add2(s2c, s2d))) - 1.f;
            float s1 = hsum2(add2(add2(s1a, s1b), add2(s1c, s1d)));
            s1 = fmaxf(s1, 1e-20f);
            tau += __fdividef(f, 2.f * s1);
        }
        {   // exact-support quadratic solve
            ull nt  = dup2(-tau);
            ull big = dup2(1e30f);
            ull s2a = 0ULL, s2b = 0ULL;
            ull s1a = 0ULL, s1b = 0ULL;
            float ca = 0.f, cb = 0.f;
            #pragma unroll
            for (int j = 0; j < 16; j++) {
                ull t0 = relu2_add(xa2[j],      nt);
                ull t1 = relu2_add(xa2[j + 16], nt);
                ffma2(s2a, t0, t0); s1a = add2(s1a, t0);
                ffma2(s2b, t1, t1); s1b = add2(s1b, t1);
                ull u0 = mul2(t0, big);
                ull u1 = mul2(t1, big);
                ca += fminf(lo2(u0), 1.f) + fminf(hi2(u0), 1.f);
                cb += fminf(lo2(u1), 1.f) + fminf(hi2(u1), 1.f);
            }
            float f  = hsum2(add2(s2a, s2b)) - 1.f;
            float s1 = fmaxf(hsum2(add2(s1a, s1b)), 1e-20f);
            float k  = ca + cb;
            float disc = fmaxf(fmaf(-k, f, s1 * s1), 0.f);
            tau += f / (s1 + sqrtf(disc));
        }
        {   // p = relu^2, normalize
            ull nt = dup2(-tau);
            ull s0 = 0ULL, s1 = 0ULL;
            #pragma unroll
            for (int p = 0; p < 16; p++) {
                ull t0 = relu2_add(xa2[p],      nt);
                ull t1 = relu2_add(xa2[p + 16], nt);
                xa2[p]      = mul2(t0, t0);
                xa2[p + 16] = mul2(t1, t1);
                ffma2(s0, t0, t0);
                ffma2(s1, t1, t1);
            }
            float rs = 1.f / hsum2(add2(s0, s1));
            ull rs2 = dup2(rs);
            #pragma unroll
            for (int p = 0; p < 32; p++) xa2[p] = mul2(xa2[p], rs2);
        }
    } else {
        float xs[64];
        #pragma unroll
        for (int p = 0; p < 32; p++) { xs[2 * p] = lo2(xa2[p]); xs[2 * p + 1] = hi2(xa2[p]); }
        float tau_lo = mx - 1.f;
        float dm     = 1.f - exp2f(-6.f * am1);
        float tau_m  = tau_lo;
        float f_lo = -1.f;
        #pragma unroll
        for (int j = 0; j < 64; j++) {
            float z = xs[j] - tau_lo;
            f_lo += (z > 0.f) ? powf(fmaxf(z, 1e-30f), inv) : 0.f;
        }
        for (int it = 0; it < NITER; it++) {
            dm *= 0.5f;
            tau_m = tau_lo + dm;
            float fm = -1.f;
            #pragma unroll
            for (int j = 0; j < 64; j++) {
                float z = xs[j] - tau_m;
                fm += (z > 0.f) ? powf(fmaxf(z, 1e-30f), inv) : 0.f;
            }
            if (fm * f_lo >= 0.f) tau_lo = tau_m;
        }
        float s = 0.f;
        #pragma unroll
        for (int j = 0; j < 64; j++) {
            float z = xs[j] - tau_m;
            float p = (z > 0.f) ? powf(fmaxf(z, 1e-30f), inv) : 0.f;
            xs[j] = p;
            s += p;
        }
        float rs = 1.f / s;
        #pragma unroll
        for (int p = 0; p < 32; p++) xa2[p] = pack2(xs[2 * p] * rs, xs[2 * p + 1] * rs);
    }

    // res[h][i] = sum_j att[i][j] * v[h][j]  -> bf16 hi/lo
    #pragma unroll
    for (int h = 0; h < NH; h++) {
        const float4* vrow = (const float4*)(sm + lt * TOKB + 17408 + h * 256);
        ull c0 = 0ULL, c1 = 0ULL;
        #pragma unroll
        for (int j4 = 0; j4 < 8; j4++) {
            float4 v0 = vrow[j4];
            float4 v1 = vrow[j4 + 8];
            ffma2(c0, xa2[j4 * 2 + 0],      pack2(v0.x, v0.y));
            ffma2(c0, xa2[j4 * 2 + 1],      pack2(v0.z, v0.w));
            ffma2(c1, xa2[16 + j4 * 2 + 0], pack2(v1.x, v1.y));
            ffma2(c1, xa2[16 + j4 * 2 + 1], pack2(v1.z, v1.w));
        }
        float r = hsum2(add2(c0, c1));
        __nv_bfloat16 hb = __float2bfloat16(r);
        __nv_bfloat16 lb = __float2bfloat16(r - __bfloat162float(hb));
        size_t o = (size_t)token * HE + h * 64 + i;
        g_res_hi[o] = hb;
        g_res_lo[o] = lb;
    }
}

// ---------------------------------------------------------------------------
// K3 (mma.sync bf16 split): output projection with register prefetch.
// CTA = 64 tokens x 64 outputs, K=512 in 8 chunks; LDG of chunk kc+1 hides
// under chunk kc's mma.
// ---------------------------------------------------------------------------
__global__ __launch_bounds__(256) void k_out(
    const float* __restrict__ bu, float* __restrict__ out)
{
    __shared__ __align__(16) __nv_bfloat16 sA[2][64 * 64];
    __shared__ __align__(16) __nv_bfloat16 sB[2][64 * 64];
    const int tid  = threadIdx.x;
    const int tok0 = blockIdx.x * 64;

    const int wid   = tid >> 5, lane = tid & 31;
    const int warpM = wid >> 1, warpN = wid & 1;

    float acc[4][4];
    #pragma unroll
    for (int n = 0; n < 4; n++)
        #pragma unroll
        for (int k = 0; k < 4; k++) acc[n][k] = 0.f;

    const uint32_t aB[2] = { smem_u32(sA[0]), smem_u32(sA[1]) };
    const uint32_t bB[2] = { smem_u32(sB[0]), smem_u32(sB[1]) };
    const int pa[3] = {0, 1, 0}, pb[3] = {0, 0, 1};

    const int arow0 = warpM * 16 + (lane & 15);
    const int brow0 = warpN * 32 + (lane & 15);
    const int chi   = lane >> 4;

    uint32_t offA[4], offB[4];
    #pragma unroll
    for (int kk = 0; kk < 4; kk++) {
        int cc = kk * 2 + chi;
        offA[kk] = (uint32_t)((arow0 * 8 + (cc ^ (arow0 & 7))) << 4);
        offB[kk] = (uint32_t)((brow0 * 8 + (cc ^ (brow0 & 7))) << 4);
    }

    // prefetch registers: [slot][hi/lo]
    uint4 pA[2][2], pB[2][2];
    const int prow0 = tid >> 3, pc = tid & 7;   // slot0: idx=tid, slot1: idx=tid+256
    const int prow1 = (tid + 256) >> 3;
    const int poff0 = prow0 * 8 + (pc ^ (prow0 & 7));
    const int poff1 = prow1 * 8 + (pc ^ (prow1 & 7));

    #define FETCH(kc) do { \
        size_t a0 = (size_t)(tok0 + prow0) * HE + (kc) * 64 + pc * 8; \
        size_t a1 = (size_t)(tok0 + prow1) * HE + (kc) * 64 + pc * 8; \
        pA[0][0] = *(const uint4*)(g_res_hi + a0); \
        pA[0][1] = *(const uint4*)(g_res_lo + a0); \
        pA[1][0] = *(const uint4*)(g_res_hi + a1); \
        pA[1][1] = *(const uint4*)(g_res_lo + a1); \
        size_t b0 = (size_t)prow0 * HE + (kc) * 64 + pc * 8; \
        size_t b1 = (size_t)prow1 * HE + (kc) * 64 + pc * 8; \
        pB[0][0] = *(const uint4*)(g_wuh + b0); \
        pB[0][1] = *(const uint4*)(g_wul + b0); \
        pB[1][0] = *(const uint4*)(g_wuh + b1); \
        pB[1][1] = *(const uint4*)(g_wul + b1); \
    } while (0)

    FETCH(0);
    for (int kc = 0; kc < 8; kc++) {
        __syncthreads();
        ((uint4*)sA[0])[poff0] = pA[0][0];
        ((uint4*)sA[1])[poff0] = pA[0][1];
        ((uint4*)sA[0])[poff1] = pA[1][0];
        ((uint4*)sA[1])[poff1] = pA[1][1];
        ((uint4*)sB[0])[poff0] = pB[0][0];
        ((uint4*)sB[1])[poff0] = pB[0][1];
        ((uint4*)sB[0])[poff1] = pB[1][0];
        ((uint4*)sB[1])[poff1] = pB[1][1];
        __syncthreads();
        if (kc < 7) FETCH(kc + 1);

        #pragma unroll
        for (int p = 0; p < 3; p++) {
            uint32_t ab = aB[pa[p]], bb = bB[pb[p]];
            #pragma unroll
            for (int kk = 0; kk < 4; kk++) {
                uint32_t a0, a1, a2, a3;
                ldsm4(a0, a1, a2, a3, ab + offA[kk]);
                uint32_t b0, b1, b2, b3, b4, b5, b6, b7;
                ldsm4(b0, b1, b2, b3, bb + offB[kk]);
                ldsm4(b4, b5, b6, b7, bb + offB[kk] + 2048);
                mma16816(acc[0], a0, a1, a2, a3, b0, b2);
                mma16816(acc[1], a0, a1, a2, a3, b1, b3);
                mma16816(acc[2], a0, a1, a2, a3, b4, b6);
                mma16816(acc[3], a0, a1, a2, a3, b5, b7);
            }
        }
    }

    const int rbase = tok0 + warpM * 16 + (lane >> 2);
    const int cbase = warpN * 32 + (lane & 3) * 2;
    #pragma unroll
    for (int nt = 0; nt < 4; nt++) {
        int col = cbase + nt * 8;
        float bv0 = __ldg(&bu[col]);
        float bv1 = __ldg(&bu[col + 1]);
        float2 e0 = make_float2(acc[nt][0] + bv0, acc[nt][1] + bv1);
        float2 e1 = make_float2(acc[nt][2] + bv0, acc[nt][3] + bv1);
        *(float2*)(out + (size_t)rbase * 64 + col)       = e0;
        *(float2*)(out + (size_t)(rbase + 8) * 64 + col) = e1;
    }
}

// ---------------------------------------------------------------------------
extern "C" void kernel_launch(void* const* d_in, const int* in_sizes, int n_in,
                              void* d_out, int out_size)
{
    const float* x     = (const float*)d_in[0];
    const float* alpha = (const float*)d_in[1];
    const float* Wk    = (const float*)d_in[2];
    const float* bk    = (const float*)d_in[3];
    const float* Wq    = (const float*)d_in[4];
    const float* bq    = (const float*)d_in[5];
    const float* Wv    = (const float*)d_in[6];
    const float* bv    = (const float*)d_in[7];
    const float* Wu    = (const float*)d_in[8];
    const float* bu    = (const float*)d_in[9];
    float* out = (float*)d_out;

    cudaFuncSetAttribute(k_attn, cudaFuncAttributeMaxDynamicSharedMemorySize, ATTN_SMEM);

    int prep_blocks = (NXP + NWP + NUP + 255) / 256;
    k_prep<<<prep_blocks, 256>>>(x, Wq, Wk, Wv, Wu);
    k_qkv<<<dim3(128, 24), 256>>>(bq, bk, bv, alpha);
    k_attn<<<NTOK / 4, 256, ATTN_SMEM>>>(alpha);
    k_out<<<NTOK / 64, 256>>>(bu, out);
}

// round 13
// speedup vs baseline: 1.3571x; 1.3571x over previous
#include <cuda_runtime.h>
#include <cuda_bf16.h>
#include <math.h>
#include <stdint.h>

#define NTOK   16384
#define NH     8
#define HE     512
#define QKVDIM 1536
#define NEWTON 3
#define NITER  16

typedef unsigned long long ull;

// Scratch (static device memory — allocation-free)
__device__ float         g_qkv[NTOK * QKVDIM];  // q (pre-scaled) | k | v
__device__ __nv_bfloat16 g_res_hi[NTOK * HE];
__device__ __nv_bfloat16 g_res_lo[NTOK * HE];
// Pre-split bf16 hi/lo operands (filled once by k_prep)
__device__ __nv_bfloat16 g_xh[NTOK * 64],  g_xl[NTOK * 64];
__device__ __nv_bfloat16 g_wh[1536 * 64],  g_wl[1536 * 64];   // [Wq;Wk;Wv]
__device__ __nv_bfloat16 g_wuh[64 * 512],  g_wul[64 * 512];

// ======================= helpers ===========================================
__device__ __forceinline__ uint32_t smem_u32(const void* p) {
    uint32_t a;
    asm("{ .reg .u64 t; cvta.to.shared.u64 t, %1; cvt.u32.u64 %0, t; }" : "=r"(a) : "l"(p));
    return a;
}
__device__ __forceinline__ void ldsm4(uint32_t& r0, uint32_t& r1, uint32_t& r2, uint32_t& r3,
                                      uint32_t a) {
    asm volatile("ldmatrix.sync.aligned.m8n8.x4.shared.b16 {%0,%1,%2,%3}, [%4];"
                 : "=r"(r0), "=r"(r1), "=r"(r2), "=r"(r3) : "r"(a));
}
__device__ __forceinline__ void mma16816(float* d, uint32_t a0, uint32_t a1, uint32_t a2,
                                         uint32_t a3, uint32_t b0, uint32_t b1) {
    asm volatile(
        "mma.sync.aligned.m16n8k16.row.col.f32.bf16.bf16.f32 "
        "{%0,%1,%2,%3}, {%4,%5,%6,%7}, {%8,%9}, {%0,%1,%2,%3};"
        : "+f"(d[0]), "+f"(d[1]), "+f"(d[2]), "+f"(d[3])
        : "r"(a0), "r"(a1), "r"(a2), "r"(a3), "r"(b0), "r"(b1));
}
__device__ __forceinline__ void split2(float a, float b, uint32_t& hp, uint32_t& lp) {
    __nv_bfloat162 h = __floats2bfloat162_rn(a, b);
    float2 hf = __bfloat1622float2(h);
    __nv_bfloat162 l = __floats2bfloat162_rn(a - hf.x, b - hf.y);
    hp = *reinterpret_cast<uint32_t*>(&h);
    lp = *reinterpret_cast<uint32_t*>(&l);
}

// ---------------- f32x2 packed-math helpers (k_attn) -----------------------
__device__ __forceinline__ ull pack2(float lo, float hi) {
    ull r; asm("mov.b64 %0, {%1, %2};" : "=l"(r) : "f"(lo), "f"(hi)); return r;
}
__device__ __forceinline__ ull dup2(float v) { return pack2(v, v); }
__device__ __forceinline__ float lo2(ull v) {
    float f; asm("{ .reg .b32 hi; mov.b64 {%0, hi}, %1; }" : "=f"(f) : "l"(v)); return f;
}
__device__ __forceinline__ float hi2(ull v) {
    float f; asm("{ .reg .b32 lo; mov.b64 {lo, %0}, %1; }" : "=f"(f) : "l"(v)); return f;
}
__device__ __forceinline__ void ffma2(ull& d, ull a, ull b) {
    asm("fma.rn.f32x2 %0, %1, %2, %0;" : "+l"(d) : "l"(a), "l"(b));
}
__device__ __forceinline__ ull add2(ull a, ull b) {
    ull r; asm("add.rn.f32x2 %0, %1, %2;" : "=l"(r) : "l"(a), "l"(b)); return r;
}
__device__ __forceinline__ ull mul2(ull a, ull b) {
    ull r; asm("mul.rn.f32x2 %0, %1, %2;" : "=l"(r) : "l"(a), "l"(b)); return r;
}
__device__ __forceinline__ float hsum2(ull v) { return lo2(v) + hi2(v); }
__device__ __forceinline__ ull relu2_add(ull x2, ull nt2) {
    ull r;
    asm("{\n\t"
        ".reg .f32 lo, hi;\n\t"
        "add.rn.f32x2 %0, %1, %2;\n\t"
        "mov.b64 {lo, hi}, %0;\n\t"
        "max.f32 lo, lo, 0f00000000;\n\t"
        "max.f32 hi, hi, 0f00000000;\n\t"
        "mov.b64 %0, {lo, hi};\n\t"
        "}" : "=l"(r) : "l"(x2), "l"(nt2));
    return r;
}

// ---------------------------------------------------------------------------
// K0: one-time bf16 hi/lo split of x, [Wq;Wk;Wv], Wu.
// ---------------------------------------------------------------------------
#define NXP  (NTOK * 64 / 2)
#define NWP  (1536 * 64 / 2)
#define NUP  (64 * 512 / 2)
__global__ __launch_bounds__(256) void k_prep(
    const float* __restrict__ x,
    const float* __restrict__ Wq, const float* __restrict__ Wk,
    const float* __restrict__ Wv, const float* __restrict__ Wu)
{
    int idx = blockIdx.x * 256 + threadIdx.x;
    const float* src; __nv_bfloat16* dh; __nv_bfloat16* dl; int p;
    if (idx < NXP)                  { src = x;  dh = g_xh;  dl = g_xl;  p = idx; }
    else if (idx < NXP + NWP) {
        p = idx - NXP;
        int f = p * 2;
        if (f < 32768)      { src = Wq; dh = g_wh; dl = g_wl; }
        else if (f < 65536) { src = Wk - 32768; dh = g_wh; dl = g_wl; }
        else                { src = Wv - 65536; dh = g_wh; dl = g_wl; }
    }
    else if (idx < NXP + NWP + NUP) { p = idx - NXP - NWP; src = Wu; dh = g_wuh; dl = g_wul; }
    else return;
    float2 v = *(const float2*)(src + (size_t)p * 2);
    uint32_t hp, lp;
    split2(v.x, v.y, hp, lp);
    ((uint32_t*)dh)[p] = hp;
    ((uint32_t*)dl)[p] = lp;
}

// ---------------------------------------------------------------------------
// K1 (mma.sync bf16 split): QKV projection, pre-split operands.
// ---------------------------------------------------------------------------
__global__ __launch_bounds__(256) void k_qkv(
    const float* __restrict__ bq, const float* __restrict__ bk,
    const float* __restrict__ bv, const float* __restrict__ alpha_p)
{
    __shared__ __align__(16) __nv_bfloat16 sA[2][128 * 64];
    __shared__ __align__(16) __nv_bfloat16 sB[2][64 * 64];
    const int tid  = threadIdx.x;
    const int bm   = blockIdx.x;
    const int tn   = blockIdx.y;
    const int oBase = tn * 64;

    const float* bias;
    if (tn < 8)       bias = bq;
    else if (tn < 16) bias = bk;
    else              bias = bv;
    const int wBase = oBase & 511;

    for (int idx = tid; idx < 1024; idx += 256) {
        int row = idx >> 3, c = idx & 7;
        size_t so = (size_t)(bm * 128 + row) * 64 + c * 8;
        int off = row * 8 + (c ^ (row & 7));
        ((uint4*)sA[0])[off] = *(const uint4*)(g_xh + so);
        ((uint4*)sA[1])[off] = *(const uint4*)(g_xl + so);
    }
    for (int idx = tid; idx < 512; idx += 256) {
        int row = idx >> 3, c = idx & 7;
        size_t so = (size_t)(tn * 64 + row) * 64 + c * 8;
        int off = row * 8 + (c ^ (row & 7));
        ((uint4*)sB[0])[off] = *(const uint4*)(g_wh + so);
        ((uint4*)sB[1])[off] = *(const uint4*)(g_wl + so);
    }
    __syncthreads();

    const int wid   = tid >> 5, lane = tid & 31;
    const int warpM = wid >> 1, warpN = wid & 1;

    float acc[2][4][4];
    #pragma unroll
    for (int m = 0; m < 2; m++)
        #pragma unroll
        for (int n = 0; n < 4; n++)
            #pragma unroll
            for (int k = 0; k < 4; k++) acc[m][n][k] = 0.f;

    const uint32_t aB[2] = { smem_u32(sA[0]), smem_u32(sA[1]) };
    const uint32_t bB[2] = { smem_u32(sB[0]), smem_u32(sB[1]) };
    const int pa[3] = {0, 1, 0}, pb[3] = {0, 0, 1};

    const int arow0 = warpM * 32 + (lane & 15);
    const int brow0 = warpN * 32 + (lane & 15);
    const int chi   = lane >> 4;

    uint32_t offA[4], offB[4];
    #pragma unroll
    for (int kk = 0; kk < 4; kk++) {
        int cc = kk * 2 + chi;
        offA[kk] = (uint32_t)((arow0 * 8 + (cc ^ (arow0 & 7))) << 4);
        offB[kk] = (uint32_t)((brow0 * 8 + (cc ^ (brow0 & 7))) << 4);
    }

    #pragma unroll
    for (int p = 0; p < 3; p++) {
        uint32_t ab = aB[pa[p]], bb = bB[pb[p]];
        #pragma unroll
        for (int kk = 0; kk < 4; kk++) {
            uint32_t a0, a1, a2, a3, a4, a5, a6, a7;
            ldsm4(a0, a1, a2, a3, ab + offA[kk]);
            ldsm4(a4, a5, a6, a7, ab + offA[kk] + 2048);
            uint32_t b0, b1, b2, b3, b4, b5, b6, b7;
            ldsm4(b0, b1, b2, b3, bb + offB[kk]);
            ldsm4(b4, b5, b6, b7, bb + offB[kk] + 2048);
            mma16816(acc[0][0], a0, a1, a2, a3, b0, b2);
            mma16816(acc[0][1], a0, a1, a2, a3, b1, b3);
            mma16816(acc[0][2], a0, a1, a2, a3, b4, b6);
            mma16816(acc[0][3], a0, a1, a2, a3, b5, b7);
            mma16816(acc[1][0], a4, a5, a6, a7, b0, b2);
            mma16816(acc[1][1], a4, a5, a6, a7, b1, b3);
            mma16816(acc[1][2], a4, a5, a6, a7, b4, b6);
            mma16816(acc[1][3], a4, a5, a6, a7, b5, b7);
        }
    }

    const float am1   = __ldg(alpha_p) - 1.f;
    const float scale = (tn < 8) ? am1 * 0.125f : 1.f;
    const int rbase = bm * 128 + warpM * 32 + (lane >> 2);
    const int cbase = warpN * 32 + (lane & 3) * 2;
    #pragma unroll
    for (int mt = 0; mt < 2; mt++)
        #pragma unroll
        for (int nt = 0; nt < 4; nt++) {
            int col = cbase + nt * 8;
            float bv0 = __ldg(&bias[wBase + col]);
            float bv1 = __ldg(&bias[wBase + col + 1]);
            int row0 = rbase + mt * 16;
            float2 e0 = make_float2((acc[mt][nt][0] + bv0) * scale,
                                    (acc[mt][nt][1] + bv1) * scale);
            float2 e1 = make_float2((acc[mt][nt][2] + bv0) * scale,
                                    (acc[mt][nt][3] + bv1) * scale);
            *(float2*)(g_qkv + (size_t)row0 * QKVDIM + oBase + col)       = e0;
            *(float2*)(g_qkv + (size_t)(row0 + 8) * QKVDIM + oBase + col) = e1;
        }
}

// ---------------------------------------------------------------------------
// K2: scores + entmax (3 Newton + exact-support quadratic solve) + att@V^T.
// 4 tokens/CTA, 64 threads per token, one score row per thread in regs.
// ---------------------------------------------------------------------------
__global__ __launch_bounds__(256) void k_attn(const float* __restrict__ alpha_p)
{
    __shared__ float kv[4][1024];
    const int tid   = threadIdx.x;
    const int tok0  = blockIdx.x * 4;
    const int lt    = tid >> 6;
    const int i     = tid & 63;
    const int token = tok0 + lt;

    {
        int f = tid;
        #pragma unroll
        for (int rep = 0; rep < 4; rep++, f += 256) {
            int t    = f >> 8;
            int idx4 = f & 255;
            float4 v = *(const float4*)(g_qkv + (size_t)(tok0 + t) * QKVDIM + 512 + idx4 * 4);
            *(float4*)(&kv[t][idx4 * 4]) = v;
        }
    }
    float q[NH];
    #pragma unroll
    for (int h = 0; h < NH; h++)
        q[h] = g_qkv[(size_t)token * QKVDIM + h * 64 + i];
    __syncthreads();

    const float am1 = alpha_p[0] - 1.f;
    const float inv = 1.f / am1;
    const bool fast = fabsf(inv - 2.f) < 1e-4f;

    ull xa2[32];
    #pragma unroll
    for (int p = 0; p < 32; p++) xa2[p] = 0ULL;
    #pragma unroll
    for (int h = 0; h < NH; h++) {
        ull q2 = dup2(q[h]);
        const float4* krow = (const float4*)&kv[lt][h * 64];
        #pragma unroll
        for (int j4 = 0; j4 < 16; j4++) {
            float4 kk = krow[j4];
            ffma2(xa2[j4 * 2 + 0], q2, pack2(kk.x, kk.y));
            ffma2(xa2[j4 * 2 + 1], q2, pack2(kk.z, kk.w));
        }
    }

    float mx = -3.4e38f;
    #pragma unroll
    for (int p = 0; p < 32; p++)
        mx = fmaxf(mx, fmaxf(lo2(xa2[p]), hi2(xa2[p])));

    float tau = mx - 1.f;

    if (fast) {
        // -------- 3 Newton iterations (monotone from below) --------
        for (int it = 0; it < NEWTON; it++) {
            ull nt = dup2(-tau);
            ull s2a = 0ULL, s2b = 0ULL, s2c = 0ULL, s2d = 0ULL;
            ull s1a = 0ULL, s1b = 0ULL, s1c = 0ULL, s1d = 0ULL;
            #pragma unroll
            for (int j = 0; j < 8; j++) {
                ull t;
                t = relu2_add(xa2[j],      nt); ffma2(s2a, t, t); s1a = add2(s1a, t);
                t = relu2_add(xa2[j +  8], nt); ffma2(s2b, t, t); s1b = add2(s1b, t);
                t = relu2_add(xa2[j + 16], nt); ffma2(s2c, t, t); s1c = add2(s1c, t);
                t = relu2_add(xa2[j + 24], nt); ffma2(s2d, t, t); s1d = add2(s1d, t);
            }
            float f  = hsum2(add2(add2(s2a, s2b), add2(s2c, s2d))) - 1.f;
            float s1 = hsum2(add2(add2(s1a, s1b), add2(s1c, s1d)));
            s1 = fmaxf(s1, 1e-20f);
            tau += __fdividef(f, 2.f * s1);
        }
        // -------- exact-support quadratic solve --------
        {
            ull nt  = dup2(-tau);
            ull big = dup2(1e30f);
            ull s2a = 0ULL, s2b = 0ULL;
            ull s1a = 0ULL, s1b = 0ULL;
            float ca = 0.f, cb = 0.f;
            #pragma unroll
            for (int j = 0; j < 16; j++) {
                ull t0 = relu2_add(xa2[j],      nt);
                ull t1 = relu2_add(xa2[j + 16], nt);
                ffma2(s2a, t0, t0); s1a = add2(s1a, t0);
                ffma2(s2b, t1, t1); s1b = add2(s1b, t1);
                ull u0 = mul2(t0, big);
                ull u1 = mul2(t1, big);
                ca += fminf(lo2(u0), 1.f) + fminf(hi2(u0), 1.f);
                cb += fminf(lo2(u1), 1.f) + fminf(hi2(u1), 1.f);
            }
            float f  = hsum2(add2(s2a, s2b)) - 1.f;
            float s1 = fmaxf(hsum2(add2(s1a, s1b)), 1e-20f);
            float k  = ca + cb;
            float disc = fmaxf(fmaf(-k, f, s1 * s1), 0.f);
            tau += f / (s1 + sqrtf(disc));
        }
        // -------- p = relu(xa - tau)^2, normalize --------
        {
            ull nt = dup2(-tau);
            ull s0 = 0ULL, s1 = 0ULL;
            #pragma unroll
            for (int p = 0; p < 16; p++) {
                ull t0 = relu2_add(xa2[p],      nt);
                ull t1 = relu2_add(xa2[p + 16], nt);
                xa2[p]      = mul2(t0, t0);
                xa2[p + 16] = mul2(t1, t1);
                ffma2(s0, t0, t0);
                ffma2(s1, t1, t1);
            }
            float rs = 1.f / hsum2(add2(s0, s1));
            ull rs2 = dup2(rs);
            #pragma unroll
            for (int p = 0; p < 32; p++) xa2[p] = mul2(xa2[p], rs2);
        }
    } else {
        float xs[64];
        #pragma unroll
        for (int p = 0; p < 32; p++) { xs[2 * p] = lo2(xa2[p]); xs[2 * p + 1] = hi2(xa2[p]); }
        float tau_lo = mx - 1.f;
        float dm     = 1.f - exp2f(-6.f * am1);
        float tau_m  = tau_lo;
        float f_lo = -1.f;
        #pragma unroll
        for (int j = 0; j < 64; j++) {
            float z = xs[j] - tau_lo;
            f_lo += (z > 0.f) ? powf(fmaxf(z, 1e-30f), inv) : 0.f;
        }
        for (int it = 0; it < NITER; it++) {
            dm *= 0.5f;
            tau_m = tau_lo + dm;
            float fm = -1.f;
            #pragma unroll
            for (int j = 0; j < 64; j++) {
                float z = xs[j] - tau_m;
                fm += (z > 0.f) ? powf(fmaxf(z, 1e-30f), inv) : 0.f;
            }
            if (fm * f_lo >= 0.f) tau_lo = tau_m;
        }
        float s = 0.f;
        #pragma unroll
        for (int j = 0; j < 64; j++) {
            float z = xs[j] - tau_m;
            float p = (z > 0.f) ? powf(fmaxf(z, 1e-30f), inv) : 0.f;
            xs[j] = p;
            s += p;
        }
        float rs = 1.f / s;
        #pragma unroll
        for (int p = 0; p < 32; p++) xa2[p] = pack2(xs[2 * p] * rs, xs[2 * p + 1] * rs);
    }

    // res[h][i] = sum_j att[i][j] * v[h][j]  -> bf16 hi/lo
    #pragma unroll
    for (int h = 0; h < NH; h++) {
        const float4* vrow = (const float4*)&kv[lt][512 + h * 64];
        ull c0 = 0ULL, c1 = 0ULL;
        #pragma unroll
        for (int j4 = 0; j4 < 8; j4++) {
            float4 v0 = vrow[j4];
            float4 v1 = vrow[j4 + 8];
            ffma2(c0, xa2[j4 * 2 + 0],      pack2(v0.x, v0.y));
            ffma2(c0, xa2[j4 * 2 + 1],      pack2(v0.z, v0.w));
            ffma2(c1, xa2[16 + j4 * 2 + 0], pack2(v1.x, v1.y));
            ffma2(c1, xa2[16 + j4 * 2 + 1], pack2(v1.z, v1.w));
        }
        float r = hsum2(add2(c0, c1));
        __nv_bfloat16 hb = __float2bfloat16(r);
        __nv_bfloat16 lb = __float2bfloat16(r - __bfloat162float(hb));
        size_t o = (size_t)token * HE + h * 64 + i;
        g_res_hi[o] = hb;
        g_res_lo[o] = lb;
    }
}

// ---------------------------------------------------------------------------
// K3 (mma.sync bf16 split): output projection with register prefetch.
// ---------------------------------------------------------------------------
__global__ __launch_bounds__(256) void k_out(
    const float* __restrict__ bu, float* __restrict__ out)
{
    __shared__ __align__(16) __nv_bfloat16 sA[2][64 * 64];
    __shared__ __align__(16) __nv_bfloat16 sB[2][64 * 64];
    const int tid  = threadIdx.x;
    const int tok0 = blockIdx.x * 64;

    const int wid   = tid >> 5, lane = tid & 31;
    const int warpM = wid >> 1, warpN = wid & 1;

    float acc[4][4];
    #pragma unroll
    for (int n = 0; n < 4; n++)
        #pragma unroll
        for (int k = 0; k < 4; k++) acc[n][k] = 0.f;

    const uint32_t aB[2] = { smem_u32(sA[0]), smem_u32(sA[1]) };
    const uint32_t bB[2] = { smem_u32(sB[0]), smem_u32(sB[1]) };
    const int pa[3] = {0, 1, 0}, pb[3] = {0, 0, 1};

    const int arow0 = warpM * 16 + (lane & 15);
    const int brow0 = warpN * 32 + (lane & 15);
    const int chi   = lane >> 4;

    uint32_t offA[4], offB[4];
    #pragma unroll
    for (int kk = 0; kk < 4; kk++) {
        int cc = kk * 2 + chi;
        offA[kk] = (uint32_t)((arow0 * 8 + (cc ^ (arow0 & 7))) << 4);
        offB[kk] = (uint32_t)((brow0 * 8 + (cc ^ (brow0 & 7))) << 4);
    }

    uint4 pA[2][2], pB[2][2];
    const int prow0 = tid >> 3, pc = tid & 7;
    const int prow1 = (tid + 256) >> 3;
    const int poff0 = prow0 * 8 + (pc ^ (prow0 & 7));
    const int poff1 = prow1 * 8 + (pc ^ (prow1 & 7));

    #define FETCH(kc) do { \
        size_t a0 = (size_t)(tok0 + prow0) * HE + (kc) * 64 + pc * 8; \
        size_t a1 = (size_t)(tok0 + prow1) * HE + (kc) * 64 + pc * 8; \
        pA[0][0] = *(const uint4*)(g_res_hi + a0); \
        pA[0][1] = *(const uint4*)(g_res_lo + a0); \
        pA[1][0] = *(const uint4*)(g_res_hi + a1); \
        pA[1][1] = *(const uint4*)(g_res_lo + a1); \
        size_t b0 = (size_t)prow0 * HE + (kc) * 64 + pc * 8; \
        size_t b1 = (size_t)prow1 * HE + (kc) * 64 + pc * 8; \
        pB[0][0] = *(const uint4*)(g_wuh + b0); \
        pB[0][1] = *(const uint4*)(g_wul + b0); \
        pB[1][0] = *(const uint4*)(g_wuh + b1); \
        pB[1][1] = *(const uint4*)(g_wul + b1); \
    } while (0)

    FETCH(0);
    for (int kc = 0; kc < 8; kc++) {
        __syncthreads();
        ((uint4*)sA[0])[poff0] = pA[0][0];
        ((uint4*)sA[1])[poff0] = pA[0][1];
        ((uint4*)sA[0])[poff1] = pA[1][0];
        ((uint4*)sA[1])[poff1] = pA[1][1];
        ((uint4*)sB[0])[poff0] = pB[0][0];
        ((uint4*)sB[1])[poff0] = pB[0][1];
        ((uint4*)sB[0])[poff1] = pB[1][0];
        ((uint4*)sB[1])[poff1] = pB[1][1];
        __syncthreads();
        if (kc < 7) FETCH(kc + 1);

        #pragma unroll
        for (int p = 0; p < 3; p++) {
            uint32_t ab = aB[pa[p]], bb = bB[pb[p]];
            #pragma unroll
            for (int kk = 0; kk < 4; kk++) {
                uint32_t a0, a1, a2, a3;
                ldsm4(a0, a1, a2, a3, ab + offA[kk]);
                uint32_t b0, b1, b2, b3, b4, b5, b6, b7;
                ldsm4(b0, b1, b2, b3, bb + offB[kk]);
                ldsm4(b4, b5, b6, b7, bb + offB[kk] + 2048);
                mma16816(acc[0], a0, a1, a2, a3, b0, b2);
                mma16816(acc[1], a0, a1, a2, a3, b1, b3);
                mma16816(acc[2], a0, a1, a2, a3, b4, b6);
                mma16816(acc[3], a0, a1, a2, a3, b5, b7);
            }
        }
    }

    const int rbase = tok0 + warpM * 16 + (lane >> 2);
    const int cbase = warpN * 32 + (lane & 3) * 2;
    #pragma unroll
    for (int nt = 0; nt < 4; nt++) {
        int col = cbase + nt * 8;
        float bv0 = __ldg(&bu[col]);
        float bv1 = __ldg(&bu[col + 1]);
        float2 e0 = make_float2(acc[nt][0] + bv0, acc[nt][1] + bv1);
        float2 e1 = make_float2(acc[nt][2] + bv0, acc[nt][3] + bv1);
        *(float2*)(out + (size_t)rbase * 64 + col)       = e0;
        *(float2*)(out + (size_t)(rbase + 8) * 64 + col) = e1;
    }
}

// ---------------------------------------------------------------------------
extern "C" void kernel_launch(void* const* d_in, const int* in_sizes, int n_in,
                              void* d_out, int out_size)
{
    const float* x     = (const float*)d_in[0];
    const float* alpha = (const float*)d_in[1];
    const float* Wk    = (const float*)d_in[2];
    const float* bk    = (const float*)d_in[3];
    const float* Wq    = (const float*)d_in[4];
    const float* bq    = (const float*)d_in[5];
    const float* Wv    = (const float*)d_in[6];
    const float* bv    = (const float*)d_in[7];
    const float* Wu    = (const float*)d_in[8];
    const float* bu    = (const float*)d_in[9];
    float* out = (float*)d_out;

    int prep_blocks = (NXP + NWP + NUP + 255) / 256;
    k_prep<<<prep_blocks, 256>>>(x, Wq, Wk, Wv, Wu);
    k_qkv<<<dim3(128, 24), 256>>>(bq, bk, bv, alpha);
    k_attn<<<NTOK / 4, 256>>>(alpha);
    k_out<<<NTOK / 64, 256>>>(bu, out);
}